// round 1
// baseline (speedup 1.0000x reference)
#include <cuda_runtime.h>

// Accumulators: [0] = sum over all of pred*log(pred), [1] = sum of (-adv*slp + 0.5*adv^2)
__device__ double g_acc[2];

__global__ void init_kernel() {
    g_acc[0] = 0.0;
    g_acc[1] = 0.0;
}

// Grid-stride float4 reduction of p*log(p) over the big pred tensor.
__global__ void plogp_kernel(const float* __restrict__ pred, long long n) {
    const long long n4 = n >> 2;
    const float4* __restrict__ p4 = reinterpret_cast<const float4*>(pred);

    float s = 0.0f;
    long long idx = (long long)blockIdx.x * blockDim.x + threadIdx.x;
    const long long stride = (long long)gridDim.x * blockDim.x;

    for (; idx < n4; idx += stride) {
        float4 p = p4[idx];
        s += p.x * __logf(p.x);
        s += p.y * __logf(p.y);
        s += p.z * __logf(p.z);
        s += p.w * __logf(p.w);
    }

    // Scalar tail (n not divisible by 4) handled by global thread 0.
    if (blockIdx.x == 0 && threadIdx.x == 0) {
        for (long long i = n4 << 2; i < n; i++) {
            float v = pred[i];
            s += v * __logf(v);
        }
    }

    // Warp reduce
    #pragma unroll
    for (int o = 16; o > 0; o >>= 1)
        s += __shfl_down_sync(0xffffffffu, s, o);

    __shared__ float ws[32];
    int lane = threadIdx.x & 31;
    int wid  = threadIdx.x >> 5;
    if (lane == 0) ws[wid] = s;
    __syncthreads();

    if (threadIdx.x == 0) {
        double blk = 0.0;
        int nw = blockDim.x >> 5;
        for (int i = 0; i < nw; i++) blk += (double)ws[i];
        atomicAdd(&g_acc[0], blk);
    }
}

// One block per batch row. Computes segment log-prob sums exactly per the
// reference semantics (exclusive-cumsum seg ids; tail of LAST row zeroed),
// then reduces (-adv*slp + 0.5*adv^2) for that row.
template <int L>
__global__ void segment_kernel(const float* __restrict__ action_probs,
                               const float* __restrict__ value,
                               const float* __restrict__ critic_value,
                               const int*   __restrict__ segments,
                               int B) {
    __shared__ float logp[L];
    __shared__ int   segid[L];
    __shared__ float segsum[L + 1];
    __shared__ int   nseg_sh;
    __shared__ float ws[32];

    const int row = blockIdx.x;
    const int t   = threadIdx.x;
    const long long base = (long long)row * L;

    // Load + log
    logp[t] = __logf(action_probs[base + t]);
    __syncthreads();

    // Sequential per-row scan by thread 0 (L=512, trivial cost, deterministic).
    if (t == 0) {
        float acc = 0.0f;
        int cnt = 0;
        for (int l = 0; l < L; l++) {
            segid[l] = cnt;
            acc += logp[l];
            if (segments[base + l] != 0) {
                segsum[cnt] = acc;
                acc = 0.0f;
                cnt++;
            }
        }
        segsum[cnt] = acc;  // trailing tail segment
        nseg_sh = cnt;
    }
    __syncthreads();

    float slp = segsum[segid[t]];
    // Faithful quirk: tail positions of the LAST batch row stay zero.
    if (row == B - 1 && segid[t] == nseg_sh) slp = 0.0f;

    float adv = value[base + t] - critic_value[base + t];
    float term = -adv * slp + 0.5f * adv * adv;

    // Block reduce
    #pragma unroll
    for (int o = 16; o > 0; o >>= 1)
        term += __shfl_down_sync(0xffffffffu, term, o);

    int lane = t & 31, wid = t >> 5;
    if (lane == 0) ws[wid] = term;
    __syncthreads();

    if (t == 0) {
        double blk = 0.0;
        int nw = blockDim.x >> 5;
        for (int i = 0; i < nw; i++) blk += (double)ws[i];
        atomicAdd(&g_acc[1], blk);
    }
}

__global__ void finalize_kernel(float* __restrict__ out, double inv_BL) {
    out[0] = (float)((g_acc[1] + 0.005 * g_acc[0]) * inv_BL);
}

extern "C" void kernel_launch(void* const* d_in, const int* in_sizes, int n_in,
                              void* d_out, int out_size) {
    const float* pred         = (const float*)d_in[0];
    const float* action_probs = (const float*)d_in[1];
    const float* value        = (const float*)d_in[2];
    const float* critic_value = (const float*)d_in[3];
    const int*   segments     = (const int*)d_in[4];

    const long long n_pred = in_sizes[0];   // B*L*V
    const int BL = in_sizes[1];             // B*L
    const int L = 512;
    const int B = BL / L;

    float* out = (float*)d_out;

    init_kernel<<<1, 1>>>();

    // HBM-bound main reduction: saturate DRAM with float4 grid-stride loads.
    const int threads = 256;
    const int blocks = 148 * 8;  // ~2 waves of work per SM at occ 8
    plogp_kernel<<<blocks, threads>>>(pred, n_pred);

    segment_kernel<512><<<B, L>>>(action_probs, value, critic_value, segments, B);

    finalize_kernel<<<1, 1>>>(out, 1.0 / (double)BL);
}

// round 2
// speedup vs baseline: 1.3591x; 1.3591x over previous
#include <cuda_runtime.h>

// Fresh-written every call (no init kernel needed; deterministic).
__device__ double g_plogp_partial[4096];
__device__ double g_seg_partial[256];

#define LN2F 0.69314718055994530942f

// Fused kernel:
//  blocks [0, B)              : per-row segment log-prob + policy/value reduce
//  blocks [B, B+nPlogp)       : grid-stride p*log2(p) reduction over pred
__global__ void __launch_bounds__(512, 4)
fused_kernel(const float* __restrict__ pred, long long n4,
             const float* __restrict__ action_probs,
             const float* __restrict__ value,
             const float* __restrict__ critic_value,
             const int*   __restrict__ segments,
             int B, int nPlogp) {
    __shared__ float  sh_ws[32];

    const int t    = threadIdx.x;
    const int lane = t & 31;
    const int wid  = t >> 5;

    if (blockIdx.x < (unsigned)B) {
        // ---------------- segment path (tiny) ----------------
        __shared__ float sh_logp[512];
        __shared__ int   sh_segid[512];
        __shared__ float sh_segsum[513];
        __shared__ int   sh_nseg;

        const int L = 512;
        const int row = blockIdx.x;
        const long long base = (long long)row * L;

        sh_logp[t] = __logf(action_probs[base + t]);
        __syncthreads();

        if (t == 0) {
            float acc = 0.0f;
            int cnt = 0;
            for (int l = 0; l < L; l++) {
                sh_segid[l] = cnt;
                acc += sh_logp[l];
                if (segments[base + l] != 0) {
                    sh_segsum[cnt] = acc;
                    acc = 0.0f;
                    cnt++;
                }
            }
            sh_segsum[cnt] = acc;   // trailing tail segment
            sh_nseg = cnt;
        }
        __syncthreads();

        float slp = sh_segsum[sh_segid[t]];
        // Faithful reference quirk: tail of the LAST batch row stays zero.
        if (row == B - 1 && sh_segid[t] == sh_nseg) slp = 0.0f;

        float adv  = value[base + t] - critic_value[base + t];
        float term = -adv * slp + 0.5f * adv * adv;

        #pragma unroll
        for (int o = 16; o > 0; o >>= 1)
            term += __shfl_down_sync(0xffffffffu, term, o);
        if (lane == 0) sh_ws[wid] = term;
        __syncthreads();
        if (t == 0) {
            double blk = 0.0;
            for (int i = 0; i < 16; i++) blk += (double)sh_ws[i];
            g_seg_partial[row] = blk;
        }
        return;
    }

    // ---------------- plogp path (HBM-bound) ----------------
    const int bid = blockIdx.x - B;
    const float4* __restrict__ p4 = reinterpret_cast<const float4*>(pred);

    const long long stride = (long long)nPlogp * 512;
    long long idx = (long long)bid * 512 + t;

    float s0 = 0.0f, s1 = 0.0f, s2 = 0.0f, s3 = 0.0f;

    // Unroll x4: four independent streaming LDG.128 in flight (MLP_p1 = 4).
    while (idx + 3 * stride < n4) {
        float4 a = __ldcs(&p4[idx]);
        float4 b = __ldcs(&p4[idx + stride]);
        float4 c = __ldcs(&p4[idx + 2 * stride]);
        float4 d = __ldcs(&p4[idx + 3 * stride]);

        s0 = fmaf(a.x, __log2f(a.x), s0);
        s0 = fmaf(a.y, __log2f(a.y), s0);
        s0 = fmaf(a.z, __log2f(a.z), s0);
        s0 = fmaf(a.w, __log2f(a.w), s0);
        s1 = fmaf(b.x, __log2f(b.x), s1);
        s1 = fmaf(b.y, __log2f(b.y), s1);
        s1 = fmaf(b.z, __log2f(b.z), s1);
        s1 = fmaf(b.w, __log2f(b.w), s1);
        s2 = fmaf(c.x, __log2f(c.x), s2);
        s2 = fmaf(c.y, __log2f(c.y), s2);
        s2 = fmaf(c.z, __log2f(c.z), s2);
        s2 = fmaf(c.w, __log2f(c.w), s2);
        s3 = fmaf(d.x, __log2f(d.x), s3);
        s3 = fmaf(d.y, __log2f(d.y), s3);
        s3 = fmaf(d.z, __log2f(d.z), s3);
        s3 = fmaf(d.w, __log2f(d.w), s3);

        idx += 4 * stride;
    }
    // Remainder
    for (; idx < n4; idx += stride) {
        float4 a = __ldcs(&p4[idx]);
        s0 = fmaf(a.x, __log2f(a.x), s0);
        s0 = fmaf(a.y, __log2f(a.y), s0);
        s0 = fmaf(a.z, __log2f(a.z), s0);
        s0 = fmaf(a.w, __log2f(a.w), s0);
    }

    float s = ((s0 + s1) + (s2 + s3)) * LN2F;   // convert log2 -> ln once

    #pragma unroll
    for (int o = 16; o > 0; o >>= 1)
        s += __shfl_down_sync(0xffffffffu, s, o);
    if (lane == 0) sh_ws[wid] = s;
    __syncthreads();
    if (t == 0) {
        double blk = 0.0;
        for (int i = 0; i < 16; i++) blk += (double)sh_ws[i];
        g_plogp_partial[bid] = blk;
    }
}

// Single-block parallel finalize.
__global__ void finalize_kernel(float* __restrict__ out, int nPlogp, int B,
                                double inv_BL) {
    __shared__ double sh[32];
    const int t = threadIdx.x;

    double s = 0.0;
    for (int i = t; i < nPlogp; i += blockDim.x) s += g_plogp_partial[i];
    double plogp_total = s;

    double g = 0.0;
    for (int i = t; i < B; i += blockDim.x) g += g_seg_partial[i];

    double v = plogp_total * 0.005 + g;
    #pragma unroll
    for (int o = 16; o > 0; o >>= 1)
        v += __shfl_down_sync(0xffffffffu, v, o);

    int lane = t & 31, wid = t >> 5;
    if (lane == 0) sh[wid] = v;
    __syncthreads();
    if (t == 0) {
        double tot = 0.0;
        int nw = blockDim.x >> 5;
        for (int i = 0; i < nw; i++) tot += sh[i];
        out[0] = (float)(tot * inv_BL);
    }
}

extern "C" void kernel_launch(void* const* d_in, const int* in_sizes, int n_in,
                              void* d_out, int out_size) {
    const float* pred         = (const float*)d_in[0];
    const float* action_probs = (const float*)d_in[1];
    const float* value        = (const float*)d_in[2];
    const float* critic_value = (const float*)d_in[3];
    const int*   segments     = (const int*)d_in[4];

    const long long n_pred = in_sizes[0];   // B*L*V (divisible by 4 here)
    const int BL = in_sizes[1];             // B*L
    const int B = BL / 512;

    float* out = (float*)d_out;

    // 512 thr/block -> 4 blocks/SM -> 592 blocks/wave on 148 SMs.
    // Total grid = 1184 = exactly 2 waves; first B blocks do segment rows.
    const int totalBlocks = 1184;
    const int nPlogp = totalBlocks - B;

    fused_kernel<<<totalBlocks, 512>>>(pred, n_pred >> 2,
                                       action_probs, value, critic_value,
                                       segments, B, nPlogp);
    finalize_kernel<<<1, 1024>>>(out, nPlogp, B, 1.0 / (double)BL);
}

// round 3
// speedup vs baseline: 1.3934x; 1.0252x over previous
#include <cuda_runtime.h>

// Fresh-written every call (deterministic; no init kernel needed).
__device__ double g_plogp_partial[4096];
__device__ double g_seg_partial[256];
__device__ int    g_done_count = 0;   // reset by the last block each call

#define LN2F 0.69314718055994530942f

// Single fused kernel:
//  blocks [0, B)         : per-row segment log-prob + policy/value reduce
//  blocks [B, total)     : grid-stride p*log2(p) reduction over pred
//  the LAST block to finish sums all partials and writes the scalar output.
__global__ void __launch_bounds__(512, 4)
fused_kernel(const float* __restrict__ pred, long long n4,
             const float* __restrict__ action_probs,
             const float* __restrict__ value,
             const float* __restrict__ critic_value,
             const int*   __restrict__ segments,
             int B, int nPlogp, int totalBlocks,
             float* __restrict__ out, double inv_BL) {
    __shared__ float  sh_ws[32];
    __shared__ bool   sh_is_last;

    const int t    = threadIdx.x;
    const int lane = t & 31;
    const int wid  = t >> 5;

    if (blockIdx.x < (unsigned)B) {
        // ---------------- segment path (tiny) ----------------
        __shared__ float sh_logp[512];
        __shared__ int   sh_segid[512];
        __shared__ float sh_segsum[513];
        __shared__ int   sh_nseg;

        const int L = 512;
        const int row = blockIdx.x;
        const long long base = (long long)row * L;

        sh_logp[t] = __logf(action_probs[base + t]);
        __syncthreads();

        if (t == 0) {
            float acc = 0.0f;
            int cnt = 0;
            for (int l = 0; l < L; l++) {
                sh_segid[l] = cnt;
                acc += sh_logp[l];
                if (segments[base + l] != 0) {
                    sh_segsum[cnt] = acc;
                    acc = 0.0f;
                    cnt++;
                }
            }
            sh_segsum[cnt] = acc;   // trailing tail segment
            sh_nseg = cnt;
        }
        __syncthreads();

        float slp = sh_segsum[sh_segid[t]];
        // Faithful reference quirk: tail of the LAST batch row stays zero.
        if (row == B - 1 && sh_segid[t] == sh_nseg) slp = 0.0f;

        float adv  = value[base + t] - critic_value[base + t];
        float term = -adv * slp + 0.5f * adv * adv;

        #pragma unroll
        for (int o = 16; o > 0; o >>= 1)
            term += __shfl_down_sync(0xffffffffu, term, o);
        if (lane == 0) sh_ws[wid] = term;
        __syncthreads();
        if (t == 0) g_seg_partial[row] = (double)sh_ws[0] + sh_ws[1] + sh_ws[2] + sh_ws[3]
                                       + sh_ws[4] + sh_ws[5] + sh_ws[6] + sh_ws[7]
                                       + sh_ws[8] + sh_ws[9] + sh_ws[10] + sh_ws[11]
                                       + sh_ws[12] + sh_ws[13] + sh_ws[14] + sh_ws[15];
    } else {
        // ---------------- plogp path (HBM-bound) ----------------
        const int bid = blockIdx.x - B;
        const float4* __restrict__ p4 = reinterpret_cast<const float4*>(pred);

        const long long stride = (long long)nPlogp * 512;
        long long idx = (long long)bid * 512 + t;

        float s0 = 0.0f, s1 = 0.0f, s2 = 0.0f, s3 = 0.0f;

        // Unroll x4: four independent streaming LDG.128 in flight.
        while (idx + 3 * stride < n4) {
            float4 a = __ldcs(&p4[idx]);
            float4 b = __ldcs(&p4[idx + stride]);
            float4 c = __ldcs(&p4[idx + 2 * stride]);
            float4 d = __ldcs(&p4[idx + 3 * stride]);

            s0 = fmaf(a.x, __log2f(a.x), s0);
            s0 = fmaf(a.y, __log2f(a.y), s0);
            s0 = fmaf(a.z, __log2f(a.z), s0);
            s0 = fmaf(a.w, __log2f(a.w), s0);
            s1 = fmaf(b.x, __log2f(b.x), s1);
            s1 = fmaf(b.y, __log2f(b.y), s1);
            s1 = fmaf(b.z, __log2f(b.z), s1);
            s1 = fmaf(b.w, __log2f(b.w), s1);
            s2 = fmaf(c.x, __log2f(c.x), s2);
            s2 = fmaf(c.y, __log2f(c.y), s2);
            s2 = fmaf(c.z, __log2f(c.z), s2);
            s2 = fmaf(c.w, __log2f(c.w), s2);
            s3 = fmaf(d.x, __log2f(d.x), s3);
            s3 = fmaf(d.y, __log2f(d.y), s3);
            s3 = fmaf(d.z, __log2f(d.z), s3);
            s3 = fmaf(d.w, __log2f(d.w), s3);

            idx += 4 * stride;
        }
        for (; idx < n4; idx += stride) {
            float4 a = __ldcs(&p4[idx]);
            s0 = fmaf(a.x, __log2f(a.x), s0);
            s0 = fmaf(a.y, __log2f(a.y), s0);
            s0 = fmaf(a.z, __log2f(a.z), s0);
            s0 = fmaf(a.w, __log2f(a.w), s0);
        }

        float s = ((s0 + s1) + (s2 + s3)) * LN2F;   // log2 -> ln once

        #pragma unroll
        for (int o = 16; o > 0; o >>= 1)
            s += __shfl_down_sync(0xffffffffu, s, o);
        if (lane == 0) sh_ws[wid] = s;
        __syncthreads();
        if (t == 0) {
            double blk = 0.0;
            #pragma unroll
            for (int i = 0; i < 16; i++) blk += (double)sh_ws[i];
            g_plogp_partial[bid] = blk;
        }
    }

    // ---------------- last-block finalize ----------------
    if (t == 0) {
        __threadfence();                                   // publish partial
        int prev = atomicAdd(&g_done_count, 1);
        sh_is_last = (prev == totalBlocks - 1);
    }
    __syncthreads();
    if (!sh_is_last) return;

    // This block is last: all partials are globally visible (fence+atomic).
    __shared__ double sh_d[32];
    double v = 0.0;
    for (int i = t; i < nPlogp; i += 512) v += g_plogp_partial[i];
    v *= 0.005;
    for (int i = t; i < B; i += 512) v += g_seg_partial[i];

    #pragma unroll
    for (int o = 16; o > 0; o >>= 1)
        v += __shfl_down_sync(0xffffffffu, v, o);
    if (lane == 0) sh_d[wid] = v;
    __syncthreads();
    if (t == 0) {
        double tot = 0.0;
        #pragma unroll
        for (int i = 0; i < 16; i++) tot += sh_d[i];
        out[0] = (float)(tot * inv_BL);
        g_done_count = 0;                                  // reset for next call
    }
}

extern "C" void kernel_launch(void* const* d_in, const int* in_sizes, int n_in,
                              void* d_out, int out_size) {
    const float* pred         = (const float*)d_in[0];
    const float* action_probs = (const float*)d_in[1];
    const float* value        = (const float*)d_in[2];
    const float* critic_value = (const float*)d_in[3];
    const int*   segments     = (const int*)d_in[4];

    const long long n_pred = in_sizes[0];   // B*L*V (divisible by 4)
    const int BL = in_sizes[1];             // B*L
    const int B = BL / 512;

    float* out = (float*)d_out;

    // 512 thr/block -> 4 blocks/SM -> 592 blocks/wave on 148 SMs.
    // Total grid = 1184 = exactly 2 waves; first B blocks do segment rows.
    const int totalBlocks = 1184;
    const int nPlogp = totalBlocks - B;

    fused_kernel<<<totalBlocks, 512>>>(pred, n_pred >> 2,
                                       action_probs, value, critic_value,
                                       segments, B, nPlogp, totalBlocks,
                                       out, 1.0 / (double)BL);
}